// round 8
// baseline (speedup 1.0000x reference)
#include <cuda_runtime.h>
#include <math.h>

#define NT 1024

// Fused TT-network:  y = log_softmax( x_pad @ W1_tt @ W2_tt )
// TT x TT (matching modes) = TT with cores G_k = contract_n(c1_k, c2_k).
// Zero-pad 177->3072 => only m1=m2=0 contribute => W[256,10], j<177 used.
//
// R8 vs proven R7 (same algebra, layout/vectorization only):
//  - c1_2/c2_2 staged TRANSPOSED k-major with k padded to 52 (zeros)
//    -> G2 inner loop is float4 LDS; tile 2x3 so 540 threads (17 warps) work.
//  - A3, G34 (transposed), W stored in 12-float padded rows -> phases 3/4
//    use float4 LDS exclusively. Pads zeroed on both operands.
//  - W computed only for j<192 (max j read by the logits phase).
__global__ __launch_bounds__(NT) void tt_fused_kernel(
    const float* __restrict__ x,     // (64,177)
    const float* __restrict__ c1_0,  // (1,3,10,3)
    const float* __restrict__ c1_1,  // (3,4,20,3)
    const float* __restrict__ c1_2,  // (3,8,50,3)
    const float* __restrict__ c1_3,  // (3,4,20,3)
    const float* __restrict__ c1_4,  // (3,8,10,1)
    const float* __restrict__ c2_0,  // (1,10,1,3)
    const float* __restrict__ c2_1,  // (3,20,2,3)
    const float* __restrict__ c2_2,  // (3,50,5,3)
    const float* __restrict__ c2_3,  // (3,20,1,3)
    const float* __restrict__ c2_4,  // (3,10,1,1)
    float* __restrict__ out)         // (64,10)
{
    __shared__ float sG1[162];                 // [r1(9), p2(2), r2(9)] (m2=0)
    __shared__ float sG2[3240];                // [u(72)] x [v(45)]
    __shared__ float sG3[324];                 // [r3, m4, r4]
    __shared__ float sG4[72];                  // [r4, m5]
    __shared__ alignas(16) float sG34t[384];   // [(m4*8+m5)][12], r3-minor, pad 0
    __shared__ float sA1[9];
    __shared__ float sA2[18];                  // [p2, r2]
    __shared__ alignas(16) float sA3p[960];    // [(m3*10+c)][12], r3-minor, pad 0
    __shared__ alignas(16) float sBUF[6084];   // A: sC1t(72*52)+sC2t(45*52); B: sW12(192*12)

    float* sC1t = sBUF;            // [u(72)][52] k-major, k=50..51 zero
    float* sC2t = sBUF + 3744;     // [v(45)][52] k-major, k=50..51 zero
    float* sW12 = sBUF;            // [j(192)][12] (staging dead by phase 3)

    const int tid = threadIdx.x;

    // ---------- x prefetch: LDGs issued now, consumed in the last phase ----
    const int b5 = tid >> 4, s5 = tid & 15;
    float xv[12];
    {
        const float* xr = x + b5 * 177;
        #pragma unroll
        for (int k = 0; k < 12; k++) {
            int j = s5 + 16 * k;
            xv[k] = (j < 177) ? __ldg(xr + j) : 0.f;
        }
    }

    // ---------- Phase 0: transposed staging + G1_0, G3, G4, A1 -------------
    // c1_2 flat i = ((a2*8+m3)*50+k)*3+a3  ->  sC1t[(a2*24+m3*3+a3)*52 + k]
    for (int i = tid; i < 3600; i += NT) {
        int a3 = i % 3, k = (i / 3) % 50, m3 = (i / 150) % 8, a2 = i / 1200;
        sC1t[(a2 * 24 + m3 * 3 + a3) * 52 + k] = c1_2[i];
    }
    // c2_2 flat i = b2*750 + k*15 + p3*3 + b3  ->  sC2t[(b2*15+p3*3+b3)*52 + k]
    for (int i = tid; i < 2250; i += NT) {
        int b3 = i % 3, p3 = (i / 3) % 5, k = (i / 15) % 50, b2 = i / 750;
        sC2t[(b2 * 15 + p3 * 3 + b3) * 52 + k] = c2_2[i];
    }
    // zero k-pads
    for (int i = tid; i < 72; i += NT) { sC1t[i * 52 + 50] = 0.f; sC1t[i * 52 + 51] = 0.f; }
    for (int i = tid; i < 45; i += NT) { sC2t[i * 52 + 50] = 0.f; sC2t[i * 52 + 51] = 0.f; }

    if (tid < 162) {
        // G1_0[r1,p2,r2] = sum_n c1_1[a1,0,n,a2] * c2_1[b1,n,p2,b2]
        int o = tid;
        int r2 = o % 9, p2 = (o / 9) % 2, r1 = o / 18;
        int a1 = r1 / 3, b1 = r1 % 3, a2 = r2 / 3, b2 = r2 % 3;
        const float* pa = c1_1 + a1 * 240 + a2;          // m2=0, n-stride 3
        const float* pb = c2_1 + b1 * 120 + p2 * 3 + b2; // n-stride 6
        float acc = 0.f;
        #pragma unroll
        for (int n = 0; n < 20; n++) acc += pa[n * 3] * pb[n * 6];
        sG1[(r1 * 2 + p2) * 9 + r2] = acc;
    } else if (tid < 486) {
        // G3[r3,m4,r4]  (324)
        int o = tid - 162;
        int r4 = o % 9; int rest = o / 9;
        int m4 = rest % 4; int r3 = rest / 4;
        int a3 = r3 / 3, b3 = r3 % 3, a4 = r4 / 3, b4 = r4 % 3;
        const float* pa = c1_3 + (a3 * 4 + m4) * 60 + a4;
        const float* pb = c2_3 + b3 * 60 + b4;
        float acc = 0.f;
        #pragma unroll
        for (int n = 0; n < 20; n++) acc += pa[n * 3] * pb[n * 3];
        sG3[o] = acc;
    } else if (tid < 558) {
        // G4[r4,m5]  (72)
        int o = tid - 486;
        int m5 = o % 8, r4 = o / 8;
        int a4 = r4 / 3, b4 = r4 % 3;
        const float* pa = c1_4 + (a4 * 8 + m5) * 10;
        const float* pb = c2_4 + b4 * 10;
        float acc = 0.f;
        #pragma unroll
        for (int n = 0; n < 10; n++) acc += pa[n] * pb[n];
        sG4[r4 * 8 + m5] = acc;
    } else if (tid < 567) {
        // A1[r1]
        int r1 = tid - 558;
        int a1 = r1 / 3, b1 = r1 % 3;
        float acc = 0.f;
        #pragma unroll
        for (int n = 0; n < 10; n++) acc += c1_0[n * 3 + a1] * c2_0[n * 3 + b1];
        sA1[r1] = acc;
    }
    __syncthreads();

    // ---------- Phase 1: G2 (2x3 tiles, float4 k-blocks) | G34t | A2 -------
    if (tid < 540) {                       // 36 u-tiles x 15 v-tiles
        int u0 = (tid / 15) * 2, v0 = (tid % 15) * 3;
        const float4* A4 = (const float4*)sC1t;  // row stride 13 float4
        const float4* B4 = (const float4*)sC2t;
        float acc[2][3] = {};
        #pragma unroll
        for (int kb = 0; kb < 13; kb++) {
            float4 a0 = A4[(u0    ) * 13 + kb];
            float4 a1 = A4[(u0 + 1) * 13 + kb];
            float4 b0 = B4[(v0    ) * 13 + kb];
            float4 b1 = B4[(v0 + 1) * 13 + kb];
            float4 b2 = B4[(v0 + 2) * 13 + kb];
            acc[0][0] = fmaf(a0.x,b0.x,fmaf(a0.y,b0.y,fmaf(a0.z,b0.z,fmaf(a0.w,b0.w,acc[0][0]))));
            acc[0][1] = fmaf(a0.x,b1.x,fmaf(a0.y,b1.y,fmaf(a0.z,b1.z,fmaf(a0.w,b1.w,acc[0][1]))));
            acc[0][2] = fmaf(a0.x,b2.x,fmaf(a0.y,b2.y,fmaf(a0.z,b2.z,fmaf(a0.w,b2.w,acc[0][2]))));
            acc[1][0] = fmaf(a1.x,b0.x,fmaf(a1.y,b0.y,fmaf(a1.z,b0.z,fmaf(a1.w,b0.w,acc[1][0]))));
            acc[1][1] = fmaf(a1.x,b1.x,fmaf(a1.y,b1.y,fmaf(a1.z,b1.z,fmaf(a1.w,b1.w,acc[1][1]))));
            acc[1][2] = fmaf(a1.x,b2.x,fmaf(a1.y,b2.y,fmaf(a1.z,b2.z,fmaf(a1.w,b2.w,acc[1][2]))));
        }
        #pragma unroll
        for (int i = 0; i < 2; i++)
            #pragma unroll
            for (int j = 0; j < 3; j++) sG2[(u0 + i) * 45 + (v0 + j)] = acc[i][j];
    } else if (tid < 828) {
        // G34t[(m4*8+m5)][r3] = sum_r4 G3[r3,m4,r4] * G4[r4,m5]  (288)
        int o = tid - 540;
        int m5 = o % 8; int m4 = (o / 8) % 4; int r3 = o / 32;
        float acc = 0.f;
        #pragma unroll
        for (int r4 = 0; r4 < 9; r4++)
            acc += sG3[(r3 * 4 + m4) * 9 + r4] * sG4[r4 * 8 + m5];
        sG34t[(m4 * 8 + m5) * 12 + r3] = acc;
    } else if (tid < 924) {
        // zero pads of G34t: 32 rows x 3 pad slots
        int o = tid - 828;
        sG34t[(o / 3) * 12 + 9 + (o % 3)] = 0.f;
    } else if (tid < 942) {
        // A2[p2,r2] = sum_r1 A1[r1] * G1_0[r1,p2,r2]
        int o = tid - 924;
        int r2 = o % 9, p2 = o / 9;
        float acc = 0.f;
        #pragma unroll
        for (int r1 = 0; r1 < 9; r1++)
            acc += sA1[r1] * sG1[(r1 * 2 + p2) * 9 + r2];
        sA2[p2 * 9 + r2] = acc;
    }
    __syncthreads();

    // ---------- Phase 2: A3p[(m3*10+c)][r3] = sum_{a2,b2} A2 * G2 ----------
    if (tid < 720) {
        int o = tid;
        int r3 = o % 9; int rest = o / 9;
        int c = rest % 10; int m3 = rest / 10;
        int p2 = c / 5, p3 = c % 5;
        int a3 = r3 / 3, b3 = r3 % 3;
        float acc = 0.f;
        #pragma unroll
        for (int a2 = 0; a2 < 3; a2++)
            #pragma unroll
            for (int b2 = 0; b2 < 3; b2++)
                acc += sA2[p2 * 9 + a2 * 3 + b2]
                     * sG2[(a2 * 24 + m3 * 3 + a3) * 45 + (b2 * 15 + p3 * 3 + b3)];
        sA3p[(m3 * 10 + c) * 12 + r3] = acc;
    } else if (tid < 960) {
        // zero pads of A3p: 80 rows x 3 pad slots
        int o = tid - 720;
        sA3p[(o / 3) * 12 + 9 + (o % 3)] = 0.f;
    }
    __syncthreads();

    // ---------- Phase 3: W[j<192][c] = dot12(A3p row, G34t row) ------------
    for (int o = tid; o < 1920; o += NT) {
        int c = o % 10; int j = o / 10;
        int m5 = j % 8; int m4 = (j / 8) % 4; int m3 = j / 32;
        const float4* A4 = (const float4*)sA3p;
        const float4* B4 = (const float4*)sG34t;
        int ra = (m3 * 10 + c) * 3, rb = (m4 * 8 + m5) * 3;
        float4 a0 = A4[ra], a1 = A4[ra + 1], a2 = A4[ra + 2];
        float4 b0 = B4[rb], b1 = B4[rb + 1], b2 = B4[rb + 2];
        float acc;
        acc = fmaf(a0.x,b0.x,fmaf(a0.y,b0.y,fmaf(a0.z,b0.z, a0.w*b0.w)));
        acc = fmaf(a1.x,b1.x,fmaf(a1.y,b1.y,fmaf(a1.z,b1.z,fmaf(a1.w,b1.w,acc))));
        acc = fmaf(a2.x,b2.x,fmaf(a2.y,b2.y,fmaf(a2.z,b2.z,fmaf(a2.w,b2.w,acc))));
        sW12[j * 12 + c] = acc;
    }
    __syncthreads();

    // ---------- Phase 4: logits + log_softmax from prefetched x ------------
    {
        float acc[10];
        #pragma unroll
        for (int c = 0; c < 10; c++) acc[c] = 0.f;
        #pragma unroll
        for (int k = 0; k < 12; k++) {
            int j = s5 + 16 * k;                 // j <= 191, covered by W
            const float4* w4 = (const float4*)(sW12 + j * 12);
            float4 w0 = w4[0], w1 = w4[1], w2 = w4[2];
            float xvk = xv[k];                   // 0 for j >= 177
            acc[0] = fmaf(xvk, w0.x, acc[0]);
            acc[1] = fmaf(xvk, w0.y, acc[1]);
            acc[2] = fmaf(xvk, w0.z, acc[2]);
            acc[3] = fmaf(xvk, w0.w, acc[3]);
            acc[4] = fmaf(xvk, w1.x, acc[4]);
            acc[5] = fmaf(xvk, w1.y, acc[5]);
            acc[6] = fmaf(xvk, w1.z, acc[6]);
            acc[7] = fmaf(xvk, w1.w, acc[7]);
            acc[8] = fmaf(xvk, w2.x, acc[8]);
            acc[9] = fmaf(xvk, w2.y, acc[9]);
        }
        #pragma unroll
        for (int off = 8; off > 0; off >>= 1)
            #pragma unroll
            for (int c = 0; c < 10; c++)
                acc[c] += __shfl_down_sync(0xffffffffu, acc[c], off, 16);
        if (s5 == 0) {
            float m = -INFINITY;
            #pragma unroll
            for (int c = 0; c < 10; c++) m = fmaxf(m, acc[c]);
            float sum = 0.f;
            #pragma unroll
            for (int c = 0; c < 10; c++) sum += __expf(acc[c] - m);
            float lse = m + __logf(sum);
            #pragma unroll
            for (int c = 0; c < 10; c++) out[b5 * 10 + c] = acc[c] - lse;
        }
    }
}

extern "C" void kernel_launch(void* const* d_in, const int* in_sizes, int n_in,
                              void* d_out, int out_size) {
    const float* x    = (const float*)d_in[0];
    const float* c1_0 = (const float*)d_in[1];
    const float* c1_1 = (const float*)d_in[2];
    const float* c1_2 = (const float*)d_in[3];
    const float* c1_3 = (const float*)d_in[4];
    const float* c1_4 = (const float*)d_in[5];
    const float* c2_0 = (const float*)d_in[6];
    const float* c2_1 = (const float*)d_in[7];
    const float* c2_2 = (const float*)d_in[8];
    const float* c2_3 = (const float*)d_in[9];
    const float* c2_4 = (const float*)d_in[10];
    float* out = (float*)d_out;

    tt_fused_kernel<<<1, NT>>>(x, c1_0, c1_1, c1_2, c1_3, c1_4,
                               c2_0, c2_1, c2_2, c2_3, c2_4, out);
}

// round 9
// speedup vs baseline: 1.1425x; 1.1425x over previous
#include <cuda_runtime.h>
#include <math.h>
#include <cstdint>

#define NT 1024

// Fused TT-network:  y = log_softmax( x_pad @ W1_tt @ W2_tt )
// TT x TT (matching modes) = TT with cores G_k = contract_n(c1_k, c2_k).
// Zero-pad 177->3072 => only m1=m2=0 contribute => W[256,10], j<192 used.
//
// R9 = proven R7 split across a 2-CTA CLUSTER. c = p2*5+p3 partitions the
// heavy phases: rank0 owns p3 in {0,1,2} (c in {0,1,2,5,6,7}), rank1 owns
// p3 in {3,4} (c in {3,4,8,9}). Each CTA computes only its G2 v-columns,
// A3 c-slices, W columns, then exchanges W via DSMEM and does 32 batch rows.
// Cheap phases (G1,G3,G4,A1,A2,G34) are duplicated in both CTAs.

__device__ __forceinline__ uint32_t ctarank() {
    uint32_t r; asm("mov.u32 %0, %%cluster_ctarank;" : "=r"(r)); return r;
}
__device__ __forceinline__ void cluster_sync() {
    asm volatile("barrier.cluster.arrive.aligned;" ::: "memory");
    asm volatile("barrier.cluster.wait.aligned;" ::: "memory");
}
__device__ __forceinline__ float dsmem_ld(uint32_t laddr, uint32_t peer) {
    uint32_t raddr; float v;
    asm volatile("mapa.shared::cluster.u32 %0, %1, %2;" : "=r"(raddr) : "r"(laddr), "r"(peer));
    asm volatile("ld.shared::cluster.f32 %0, [%1];" : "=f"(v) : "r"(raddr) : "memory");
    return v;
}

__global__ __launch_bounds__(NT) __cluster_dims__(2, 1, 1)
void tt_fused_kernel(
    const float* __restrict__ x,     // (64,177)
    const float* __restrict__ c1_0,  // (1,3,10,3)
    const float* __restrict__ c1_1,  // (3,4,20,3)
    const float* __restrict__ c1_2,  // (3,8,50,3)
    const float* __restrict__ c1_3,  // (3,4,20,3)
    const float* __restrict__ c1_4,  // (3,8,10,1)
    const float* __restrict__ c2_0,  // (1,10,1,3)
    const float* __restrict__ c2_1,  // (3,20,2,3)
    const float* __restrict__ c2_2,  // (3,50,5,3)
    const float* __restrict__ c2_3,  // (3,20,1,3)
    const float* __restrict__ c2_4,  // (3,10,1,1)
    float* __restrict__ out)         // (64,10)
{
    __shared__ float sG1[162];    // [r1(9), p2(2), r2(9)]  (m2=0 slice)
    __shared__ float sG2[3240];   // [u(72)][v(45)] (only own v-cols filled)
    __shared__ float sG3[324];    // [r3, m4, r4]
    __shared__ float sG4[72];     // [r4, m5]
    __shared__ float sG34[288];   // [r3, m4, m5]
    __shared__ float sA1[9];
    __shared__ float sA2[18];     // [p2, r2]
    __shared__ float sA3[720];    // [(m3*10+c)*9+r3] (own c entries filled)
    __shared__ float sBUF[5850];  // A: sC1(3600)+sC2(2250); B: sW (tail)

    float* sC1 = sBUF;            // staged c1_2
    float* sC2 = sBUF + 3600;     // staged c2_2
    float* sW  = sBUF + 2880;     // [j(192)][10] (staging dead by W phase)

    const int tid = threadIdx.x;
    const uint32_t rank = ctarank();
    const uint32_t peer = rank ^ 1u;
    const int nc  = rank ? 4 : 6;   // own c count
    const int npc = rank ? 6 : 4;   // peer c count

    // ---------- x prefetch: this CTA's 32 batch rows, 16 lanes each --------
    const int b5 = (tid >> 4) + (int)rank * 32, s5 = tid & 15;
    float xv[12];
    if (tid < 512) {
        const float* xr = x + b5 * 177;
        #pragma unroll
        for (int k = 0; k < 12; k++) {
            int j = s5 + 16 * k;
            xv[k] = (j < 177) ? __ldg(xr + j) : 0.f;
        }
    }

    // ---------- Phase 0 (dup): stage cores; G1_0, G3, G4, A1 ---------------
    for (int i = tid; i < 3600; i += NT) sC1[i] = c1_2[i];
    for (int i = tid; i < 2250; i += NT) sC2[i] = c2_2[i];

    if (tid < 162) {
        // G1_0[r1,p2,r2] = sum_n c1_1[a1,0,n,a2] * c2_1[b1,n,p2,b2]
        int o = tid;
        int r2 = o % 9, p2 = (o / 9) % 2, r1 = o / 18;
        int a1 = r1 / 3, b1 = r1 % 3, a2 = r2 / 3, b2 = r2 % 3;
        const float* pa = c1_1 + a1 * 240 + a2;          // m2=0, n-stride 3
        const float* pb = c2_1 + b1 * 120 + p2 * 3 + b2; // n-stride 6
        float acc = 0.f;
        #pragma unroll
        for (int n = 0; n < 20; n++) acc += pa[n * 3] * pb[n * 6];
        sG1[(r1 * 2 + p2) * 9 + r2] = acc;
    } else if (tid < 486) {
        // G3[r3,m4,r4]  (324)
        int o = tid - 162;
        int r4 = o % 9; int rest = o / 9;
        int m4 = rest % 4; int r3 = rest / 4;
        int a3 = r3 / 3, b3 = r3 % 3, a4 = r4 / 3, b4 = r4 % 3;
        const float* pa = c1_3 + (a3 * 4 + m4) * 60 + a4;
        const float* pb = c2_3 + b3 * 60 + b4;
        float acc = 0.f;
        #pragma unroll
        for (int n = 0; n < 20; n++) acc += pa[n * 3] * pb[n * 3];
        sG3[o] = acc;
    } else if (tid < 558) {
        // G4[r4,m5]  (72)
        int o = tid - 486;
        int m5 = o % 8, r4 = o / 8;
        int a4 = r4 / 3, b4 = r4 % 3;
        const float* pa = c1_4 + (a4 * 8 + m5) * 10;
        const float* pb = c2_4 + b4 * 10;
        float acc = 0.f;
        #pragma unroll
        for (int n = 0; n < 10; n++) acc += pa[n] * pb[n];
        sG4[r4 * 8 + m5] = acc;
    } else if (tid < 567) {
        // A1[r1]
        int r1 = tid - 558;
        int a1 = r1 / 3, b1 = r1 % 3;
        float acc = 0.f;
        #pragma unroll
        for (int n = 0; n < 10; n++) acc += c1_0[n * 3 + a1] * c2_0[n * 3 + b1];
        sA1[r1] = acc;
    }
    __syncthreads();

    // ---------- Phase 1: G2 own v-tiles (2x3) | G34 (dup) | A2 (dup) -------
    {
        const int nvt = rank ? 6 : 9;          // own v-tiles per u-tile-row
        const int n2 = 36 * nvt;               // 324 or 216 threads
        if (tid < n2) {
            int ut = tid / nvt, vl = tid % nvt;
            int b2, p3;
            if (rank == 0) { b2 = vl / 3; p3 = vl % 3; }
            else           { b2 = vl / 2; p3 = 3 + (vl % 2); }
            int u0 = ut * 2, v0 = b2 * 15 + p3 * 3;
            int abase0 = (u0 / 3) * 150 + (u0 % 3);
            int abase1 = ((u0 + 1) / 3) * 150 + ((u0 + 1) % 3);
            int bb = b2 * 750 + p3 * 3;        // + b3 + k*15
            float a00 = 0.f, a01 = 0.f, a02 = 0.f, a10 = 0.f, a11 = 0.f, a12 = 0.f;
            #pragma unroll 5
            for (int k = 0; k < 50; k++) {
                float a0 = sC1[abase0 + k * 3];
                float a1 = sC1[abase1 + k * 3];
                float b0 = sC2[bb + k * 15];
                float b1 = sC2[bb + k * 15 + 1];
                float b2v = sC2[bb + k * 15 + 2];
                a00 = fmaf(a0, b0, a00); a01 = fmaf(a0, b1, a01); a02 = fmaf(a0, b2v, a02);
                a10 = fmaf(a1, b0, a10); a11 = fmaf(a1, b1, a11); a12 = fmaf(a1, b2v, a12);
            }
            sG2[u0 * 45 + v0] = a00; sG2[u0 * 45 + v0 + 1] = a01; sG2[u0 * 45 + v0 + 2] = a02;
            sG2[(u0 + 1) * 45 + v0] = a10; sG2[(u0 + 1) * 45 + v0 + 1] = a11; sG2[(u0 + 1) * 45 + v0 + 2] = a12;
        } else if (tid >= 540 && tid < 828) {
            // G34[r3,m4,m5] = sum_r4 G3[r3,m4,r4] * G4[r4,m5]  (288, dup)
            int o = tid - 540;
            int m5 = o % 8; int m4 = (o / 8) % 4; int r3 = o / 32;
            float acc = 0.f;
            #pragma unroll
            for (int r4 = 0; r4 < 9; r4++)
                acc += sG3[(r3 * 4 + m4) * 9 + r4] * sG4[r4 * 8 + m5];
            sG34[(r3 * 4 + m4) * 8 + m5] = acc;
        } else if (tid >= 828 && tid < 846) {
            // A2[p2,r2] = sum_r1 A1[r1] * G1_0[r1,p2,r2]  (18, dup)
            int o = tid - 828;
            int r2 = o % 9, p2 = o / 9;
            float acc = 0.f;
            #pragma unroll
            for (int r1 = 0; r1 < 9; r1++)
                acc += sA1[r1] * sG1[(r1 * 2 + p2) * 9 + r2];
            sA2[p2 * 9 + r2] = acc;
        }
    }
    __syncthreads();

    // ---------- Phase 2: A3 own c-slices -----------------------------------
    {
        int cnt = 72 * nc;                     // 432 or 288 (x9 r3 below)
        if (tid < cnt * 9 / 9 * 9 && tid < 8 * nc * 9) {
            int o = tid;
            int r3 = o % 9; int rest = o / 9;
            int ci = rest % nc; int m3 = rest / nc;
            int c = rank ? ((ci / 2) * 5 + 3 + (ci % 2)) : ((ci / 3) * 5 + (ci % 3));
            int p2 = c / 5, p3 = c % 5;
            int a3 = r3 / 3, b3 = r3 % 3;
            float acc = 0.f;
            #pragma unroll
            for (int a2 = 0; a2 < 3; a2++)
                #pragma unroll
                for (int b2 = 0; b2 < 3; b2++)
                    acc += sA2[p2 * 9 + a2 * 3 + b2]
                         * sG2[(a2 * 24 + m3 * 3 + a3) * 45 + (b2 * 15 + p3 * 3 + b3)];
            sA3[(m3 * 10 + c) * 9 + r3] = acc;
        }
    }
    __syncthreads();

    // ---------- Phase 3: W[j<192][own c] -----------------------------------
    for (int o = tid; o < 192 * nc; o += NT) {
        int ci = o % nc; int j = o / nc;
        int c = rank ? ((ci / 2) * 5 + 3 + (ci % 2)) : ((ci / 3) * 5 + (ci % 3));
        int m5 = j % 8; int m4 = (j / 8) % 4; int m3 = j / 32;
        float acc = 0.f;
        #pragma unroll
        for (int r3 = 0; r3 < 9; r3++)
            acc += sA3[(m3 * 10 + c) * 9 + r3] * sG34[(r3 * 4 + m4) * 8 + m5];
        sW[j * 10 + c] = acc;
    }
    __syncthreads();
    cluster_sync();   // peer's W columns are now written in peer's SMEM

    // ---------- Phase 4: fetch peer's W columns via DSMEM ------------------
    for (int o = tid; o < 192 * npc; o += NT) {
        int ci = o % npc; int j = o / npc;
        // peer's c-list (opposite of ours)
        int c = rank ? ((ci / 3) * 5 + (ci % 3)) : ((ci / 2) * 5 + 3 + (ci % 2));
        uint32_t laddr = (uint32_t)__cvta_generic_to_shared(&sW[j * 10 + c]);
        sW[j * 10 + c] = dsmem_ld(laddr, peer);
    }
    __syncthreads();

    // ---------- Phase 5: logits + log_softmax, 32 rows per CTA -------------
    if (tid < 512) {
        float acc[10];
        #pragma unroll
        for (int c = 0; c < 10; c++) acc[c] = 0.f;
        #pragma unroll
        for (int k = 0; k < 12; k++) {
            int j = s5 + 16 * k;                 // j <= 191
            const float* wr = sW + j * 10;
            float xvk = xv[k];                   // 0 for j >= 177
            #pragma unroll
            for (int c = 0; c < 10; c++) acc[c] = fmaf(xvk, wr[c], acc[c]);
        }
        #pragma unroll
        for (int off = 8; off > 0; off >>= 1)
            #pragma unroll
            for (int c = 0; c < 10; c++)
                acc[c] += __shfl_down_sync(0xffffffffu, acc[c], off, 16);
        if (s5 == 0) {
            float m = -INFINITY;
            #pragma unroll
            for (int c = 0; c < 10; c++) m = fmaxf(m, acc[c]);
            float sum = 0.f;
            #pragma unroll
            for (int c = 0; c < 10; c++) sum += __expf(acc[c] - m);
            float lse = m + __logf(sum);
            #pragma unroll
            for (int c = 0; c < 10; c++) out[b5 * 10 + c] = acc[c] - lse;
        }
    }

    // keep SMEM alive until peer's DSMEM reads are done
    cluster_sync();
}

extern "C" void kernel_launch(void* const* d_in, const int* in_sizes, int n_in,
                              void* d_out, int out_size) {
    const float* x    = (const float*)d_in[0];
    const float* c1_0 = (const float*)d_in[1];
    const float* c1_1 = (const float*)d_in[2];
    const float* c1_2 = (const float*)d_in[3];
    const float* c1_3 = (const float*)d_in[4];
    const float* c1_4 = (const float*)d_in[5];
    const float* c2_0 = (const float*)d_in[6];
    const float* c2_1 = (const float*)d_in[7];
    const float* c2_2 = (const float*)d_in[8];
    const float* c2_3 = (const float*)d_in[9];
    const float* c2_4 = (const float*)d_in[10];
    float* out = (float*)d_out;

    tt_fused_kernel<<<2, NT>>>(x, c1_0, c1_1, c1_2, c1_3, c1_4,
                               c2_0, c2_1, c2_2, c2_3, c2_4, out);
}